// round 4
// baseline (speedup 1.0000x reference)
#include <cuda_runtime.h>

// PLIF scan: x [B=16, T=16, C=128, H=32, W=32] fp32, scalar leak w.
//   mem = w*mem + x_t; spike = (mem >= 1); mem *= (1 - spike)
//
// Round 4: R1 body (plain ld/st, ptxas-pipelined, regs ~31, occ ~80%) inside
// a non-unrolled grid-stride loop: 1024 CTAs x 256 threads, 2 sequential
// lanes per thread -> exactly one balanced resident wave (<=7 CTAs/SM),
// no wave-quantization tail. NO cache hints (R3 showed .cs/.wt force
// full front-batching -> regs 78 -> occ 30% -> slower).

#define B_   16
#define T_   16
#define CHW4 32768                 // (128*32*32)/4 float4 per (b,t) plane
#define NV4  (B_ * CHW4)           // 524288 float4 lanes
#define TPB  256
#define NBLK 1024                  // NV4 / (2 * TPB)
#define NTHR (NBLK * TPB)          // 262144 threads, 2 lanes each

__global__ __launch_bounds__(TPB) void plif_kernel(
    const float4* __restrict__ x,
    const float*  __restrict__ wp,
    float4*       __restrict__ out)
{
    const int tid = blockIdx.x * blockDim.x + threadIdx.x;
    const float w = *wp;                     // scalar, L1-broadcast

    #pragma unroll 1
    for (int lane = tid; lane < NV4; lane += NTHR) {
        const int b = lane >> 15;                 // lane / CHW4
        const int s = lane & (CHW4 - 1);          // lane % CHW4
        const float4* xb = x   + (size_t)b * (T_ * CHW4) + s;
        float4*       ob = out + (size_t)b * (T_ * CHW4) + s;

        // Plain loads; ptxas software-pipelines to its preferred depth.
        float4 xs[T_];
        #pragma unroll
        for (int t = 0; t < T_; ++t)
            xs[t] = xb[t * CHW4];

        float m0 = 0.f, m1 = 0.f, m2 = 0.f, m3 = 0.f;

        #pragma unroll
        for (int t = 0; t < T_; ++t) {
            m0 = fmaf(w, m0, xs[t].x);
            m1 = fmaf(w, m1, xs[t].y);
            m2 = fmaf(w, m2, xs[t].z);
            m3 = fmaf(w, m3, xs[t].w);

            const float s0 = (m0 >= 1.0f) ? 1.0f : 0.0f;
            const float s1 = (m1 >= 1.0f) ? 1.0f : 0.0f;
            const float s2 = (m2 >= 1.0f) ? 1.0f : 0.0f;
            const float s3 = (m3 >= 1.0f) ? 1.0f : 0.0f;

            m0 = (s0 != 0.0f) ? 0.0f : m0;
            m1 = (s1 != 0.0f) ? 0.0f : m1;
            m2 = (s2 != 0.0f) ? 0.0f : m2;
            m3 = (s3 != 0.0f) ? 0.0f : m3;

            float4 o; o.x = s0; o.y = s1; o.z = s2; o.w = s3;
            ob[t * CHW4] = o;
        }
    }
}

extern "C" void kernel_launch(void* const* d_in, const int* in_sizes, int n_in,
                              void* d_out, int out_size)
{
    const float4* x  = (const float4*)d_in[0];
    const float*  wp = (const float*)d_in[1];
    float4* out = (float4*)d_out;

    plif_kernel<<<NBLK, TPB>>>(x, wp, out);
}

// round 5
// speedup vs baseline: 1.0428x; 1.0428x over previous
#include <cuda_runtime.h>

// PLIF scan: x [B=16, T=16, C=128, H=32, W=32] fp32, scalar leak w.
//   mem = w*mem + x_t; spike = (mem >= 1); mem *= (1 - spike)
//
// Round 5: exact R1 geometry/body (1 float4 lane per thread, 2048x256,
// plain loads -> ptxas software pipeline, regs ~31, occ ~80%) with ONE
// isolated change: __stwt on the output stream. Stores are fire-and-forget
// (no register cost, no pipeline impact); write-through skips L2
// write-allocate for data that is never re-read.
// (R3's regression came from __ldcs forcing full 16-deep load batching ->
//  regs 78 -> occ 30%; store policy was confounded there.)

#define B_   16
#define T_   16
#define CHW4 32768                 // (128*32*32)/4 float4 per (b,t) plane
#define NV4  (B_ * CHW4)           // 524288 float4 lanes
#define TPB  256

__global__ __launch_bounds__(TPB) void plif_kernel(
    const float4* __restrict__ x,
    const float*  __restrict__ wp,
    float4*       __restrict__ out)
{
    const int tid = blockIdx.x * blockDim.x + threadIdx.x;
    if (tid >= NV4) return;

    const float w = *wp;                     // scalar, L1-broadcast

    const int b = tid >> 15;                 // tid / CHW4
    const int s = tid & (CHW4 - 1);          // tid % CHW4
    const float4* xb = x   + (size_t)b * (T_ * CHW4) + s;
    float4*       ob = out + (size_t)b * (T_ * CHW4) + s;

    // Plain loads: ptxas pipelines these to its preferred depth (regs ~31).
    float4 xs[T_];
    #pragma unroll
    for (int t = 0; t < T_; ++t)
        xs[t] = xb[t * CHW4];

    float m0 = 0.f, m1 = 0.f, m2 = 0.f, m3 = 0.f;

    #pragma unroll
    for (int t = 0; t < T_; ++t) {
        m0 = fmaf(w, m0, xs[t].x);
        m1 = fmaf(w, m1, xs[t].y);
        m2 = fmaf(w, m2, xs[t].z);
        m3 = fmaf(w, m3, xs[t].w);

        const float s0 = (m0 >= 1.0f) ? 1.0f : 0.0f;
        const float s1 = (m1 >= 1.0f) ? 1.0f : 0.0f;
        const float s2 = (m2 >= 1.0f) ? 1.0f : 0.0f;
        const float s3 = (m3 >= 1.0f) ? 1.0f : 0.0f;

        m0 = (s0 != 0.0f) ? 0.0f : m0;
        m1 = (s1 != 0.0f) ? 0.0f : m1;
        m2 = (s2 != 0.0f) ? 0.0f : m2;
        m3 = (s3 != 0.0f) ? 0.0f : m3;

        float4 o; o.x = s0; o.y = s1; o.z = s2; o.w = s3;
        __stwt(&ob[t * CHW4], o);
    }
}

extern "C" void kernel_launch(void* const* d_in, const int* in_sizes, int n_in,
                              void* d_out, int out_size)
{
    const float4* x  = (const float4*)d_in[0];
    const float*  wp = (const float*)d_in[1];
    float4* out = (float4*)d_out;

    const int blocks = (NV4 + TPB - 1) / TPB;   // 2048
    plif_kernel<<<blocks, TPB>>>(x, wp, out);
}